// round 1
// baseline (speedup 1.0000x reference)
#include <cuda_runtime.h>
#include <cuda_bf16.h>

#define INV_SQRT2 0.70710678118654752440f

// One CTA per (batch b, input channel cin). Produces output channels 2*cin and 2*cin+1.
//  x row (4096) -> conv7(w1) -> BN -> GELU(exact) -> leaky -> Haar split (even/odd)
//  -> conv7(w2L)/conv3(w2H) -> Haar merge -> + w_skip*x -> leaky -> out rows.
// Shared arrays hold literal zero padding so all conv loops are branch-free.
__global__ __launch_bounds__(256, 1)
void fused_block_wavelet_down(
    const float* __restrict__ x,      // (64, 64, 4096)
    const float* __restrict__ w1,     // (128, 1, 7)
    const float* __restrict__ g1,     // (128)
    const float* __restrict__ b1,     // (128)
    const float* __restrict__ m1,     // (128)
    const float* __restrict__ v1,     // (128)
    const float* __restrict__ w2L,    // (128, 1, 7)
    const float* __restrict__ w2H,    // (128, 1, 3)
    const float* __restrict__ wskip,  // (128, 1, 1)
    float* __restrict__ out)          // (64, 128, 4096)
{
    // logical x[t]  lives at sx[t+3],  t in [0,4096): pads sx[0..2], sx[4099..4101]
    // logical xL[i] lives at sL[i+3],  i in [0,2048): pads sL[0..2], sL[2051..2053]
    // logical xH[i] lives at sH[i+1],  i in [0,2048): pads sH[0],    sH[2049]
    __shared__ float sx[4096 + 8];
    __shared__ float sL[2048 + 8];
    __shared__ float sH[2048 + 4];

    const int tid = threadIdx.x;
    const int b   = blockIdx.x >> 6;
    const int cin = blockIdx.x & 63;

    // ---- zero the pad cells (exact indices only; no overlap with loaded data) ----
    if (tid < 3) {
        sx[tid] = 0.f;  sx[4099 + tid] = 0.f;
        sL[tid] = 0.f;  sL[2051 + tid] = 0.f;
    }
    if (tid == 3) { sH[0] = 0.f; sH[2049] = 0.f; }

    // ---- load x row: 1024 float4 global loads, scatter to sx (offset +3) ----
    {
        const float4* x4 = reinterpret_cast<const float4*>(
            x + ((size_t)(b * 64 + cin) << 12));
        #pragma unroll
        for (int p = 0; p < 4; ++p) {
            int idx = tid + p * 256;          // 0..1023
            float4 v = x4[idx];
            int base = 3 + 4 * idx;
            sx[base + 0] = v.x;
            sx[base + 1] = v.y;
            sx[base + 2] = v.z;
            sx[base + 3] = v.w;
        }
    }
    __syncthreads();

    const float2* sx2 = reinterpret_cast<const float2*>(sx);  // sx2[i] = {sx[2i], sx[2i+1]}

    #pragma unroll 1
    for (int u = 0; u < 2; ++u) {
        const int oc = 2 * cin + u;

        // per-output-channel parameters (L2-broadcast loads, tiny)
        float wk[7], wL[7], wH[3];
        #pragma unroll
        for (int k = 0; k < 7; ++k) wk[k] = w1[oc * 7 + k];
        #pragma unroll
        for (int k = 0; k < 7; ++k) wL[k] = w2L[oc * 7 + k];
        #pragma unroll
        for (int k = 0; k < 3; ++k) wH[k] = w2H[oc * 3 + k];
        const float inv  = g1[oc] * rsqrtf(v1[oc] + 1e-5f);
        const float bias = b1[oc] - m1[oc] * inv;
        const float ws   = wskip[oc];

        // ---- phase 1: h pairs -> Haar coefficients sL/sH ----
        #pragma unroll
        for (int p = 0; p < 8; ++p) {
            const int i = tid + p * 256;            // 0..2047
            // window w[m] = sx_buf[2i+m], m=0..7  (conflict-free float2 reads)
            float2 a0 = sx2[i];
            float2 a1 = sx2[i + 1];
            float2 a2 = sx2[i + 2];
            float2 a3 = sx2[i + 3];
            float w[8] = {a0.x, a0.y, a1.x, a1.y, a2.x, a2.y, a3.x, a3.y};

            float h0 = 0.f, h1 = 0.f;
            #pragma unroll
            for (int k = 0; k < 7; ++k) {
                h0 = fmaf(w[k],     wk[k], h0);     // t = 2i
                h1 = fmaf(w[k + 1], wk[k], h1);     // t = 2i+1
            }
            // BN
            h0 = fmaf(h0, inv, bias);
            h1 = fmaf(h1, inv, bias);
            // exact GELU: 0.5*x*(1+erf(x/sqrt2))
            h0 = 0.5f * h0 * (1.f + erff(h0 * INV_SQRT2));
            h1 = 0.5f * h1 * (1.f + erff(h1 * INV_SQRT2));
            // LeakyReLU(0.01)
            h0 = (h0 >= 0.f) ? h0 : 0.01f * h0;
            h1 = (h1 >= 0.f) ? h1 : 0.01f * h1;
            // Haar split
            sL[i + 3] = (h0 + h1) * INV_SQRT2;
            sH[i + 1] = (h0 - h1) * INV_SQRT2;
        }
        __syncthreads();

        // ---- phase 2: depthwise convs on sL/sH, merge, skip, leaky, store ----
        float2* o2 = reinterpret_cast<float2*>(
            out + ((size_t)(b * 128 + oc) << 12));
        #pragma unroll
        for (int p = 0; p < 8; ++p) {
            const int i = tid + p * 256;            // 0..2047
            float yL = 0.f;
            #pragma unroll
            for (int j = 0; j < 7; ++j) yL = fmaf(wL[j], sL[i + j], yL);
            float yH = 0.f;
            #pragma unroll
            for (int j = 0; j < 3; ++j) yH = fmaf(wH[j], sH[i + j], yH);

            const float re = (yL + yH) * INV_SQRT2;   // output position 2i
            const float ro = (yL - yH) * INV_SQRT2;   // output position 2i+1

            const float xe = sx[2 * i + 3];           // x[2i]
            const float xo = sx[2 * i + 4];           // x[2i+1]

            float o0 = fmaf(xe, ws, re);
            float o1 = fmaf(xo, ws, ro);
            o0 = (o0 >= 0.f) ? o0 : 0.01f * o0;
            o1 = (o1 >= 0.f) ? o1 : 0.01f * o1;
            o2[i] = make_float2(o0, o1);
        }
        __syncthreads();   // protect sL/sH before next output channel reuses them
    }
}

extern "C" void kernel_launch(void* const* d_in, const int* in_sizes, int n_in,
                              void* d_out, int out_size) {
    const float* x     = (const float*)d_in[0];
    const float* w1    = (const float*)d_in[1];
    const float* g1    = (const float*)d_in[2];
    const float* b1    = (const float*)d_in[3];
    const float* m1    = (const float*)d_in[4];
    const float* v1    = (const float*)d_in[5];
    const float* w2L   = (const float*)d_in[6];
    const float* w2H   = (const float*)d_in[7];
    const float* wskip = (const float*)d_in[8];
    float* out = (float*)d_out;

    fused_block_wavelet_down<<<64 * 64, 256>>>(
        x, w1, g1, b1, m1, v1, w2L, w2H, wskip, out);
}

// round 2
// speedup vs baseline: 1.0739x; 1.0739x over previous
#include <cuda_runtime.h>
#include <cuda_bf16.h>

#define INV_SQRT2 0.70710678118654752440f

// One CTA per (batch b, input channel cin) -> output channels 2*cin, 2*cin+1.
// Tiled 4 outputs/thread with padded smem layouts so all hot accesses are
// 128-bit LDS/STS/STG:
//   x[t]  at sx[t+4]  (zeros sx[1..3], sx[4100..4102])
//   xL[i] at sL[i+4]  (zeros sL[1..3], sL[2052..2054])
//   xH[i] at sH[i+2]  (zeros sH[1],    sH[2050])
__global__ __launch_bounds__(256, 3)
void fused_block_wavelet_down(
    const float* __restrict__ x,      // (64, 64, 4096)
    const float* __restrict__ w1,     // (128, 1, 7)
    const float* __restrict__ g1,
    const float* __restrict__ b1,
    const float* __restrict__ m1,
    const float* __restrict__ v1,
    const float* __restrict__ w2L,    // (128, 1, 7)
    const float* __restrict__ w2H,    // (128, 1, 3)
    const float* __restrict__ wskip,  // (128, 1, 1)
    float* __restrict__ out)          // (64, 128, 4096)
{
    __shared__ float sx[4104];   // x row, offset +4
    __shared__ float sL[2056];   // low band, offset +4
    __shared__ float sH[2052];   // high band, offset +2

    const int tid = threadIdx.x;
    const int b   = blockIdx.x >> 6;
    const int cin = blockIdx.x & 63;

    // zero pad cells (exact indices; never overlap real data)
    if (tid < 3) {
        sx[1 + tid] = 0.f;  sx[4100 + tid] = 0.f;
        sL[1 + tid] = 0.f;  sL[2052 + tid] = 0.f;
    }
    if (tid == 3) { sH[1] = 0.f; sH[2050] = 0.f; }

    // load x row: 1024 aligned LDG.128 -> STS.128 (offset +4 keeps 16B align)
    {
        const float4* x4 = reinterpret_cast<const float4*>(
            x + ((size_t)(b * 64 + cin) << 12));
        float4* sx4w = reinterpret_cast<float4*>(sx + 4);
        #pragma unroll
        for (int p = 0; p < 4; ++p)
            sx4w[tid + p * 256] = x4[tid + p * 256];
    }
    __syncthreads();

    const float4* sx4 = reinterpret_cast<const float4*>(sx);
    const float4* sL4 = reinterpret_cast<const float4*>(sL);
    const float4* sH4 = reinterpret_cast<const float4*>(sH);
    float4* sL4w = reinterpret_cast<float4*>(sL);
    float2* sH2w = reinterpret_cast<float2*>(sH);

    #pragma unroll 1
    for (int u = 0; u < 2; ++u) {
        const int oc = 2 * cin + u;

        float wk[7], wL[7], wH[3];
        #pragma unroll
        for (int k = 0; k < 7; ++k) wk[k] = w1[oc * 7 + k];
        #pragma unroll
        for (int k = 0; k < 7; ++k) wL[k] = w2L[oc * 7 + k];
        #pragma unroll
        for (int k = 0; k < 3; ++k) wH[k] = w2H[oc * 3 + k];
        const float inv  = g1[oc] * rsqrtf(v1[oc] + 1e-5f);
        const float bias = b1[oc] - m1[oc] * inv;
        const float ws   = wskip[oc];

        // ---- phase 1: 4 Haar pairs per thread-group iteration ----
        #pragma unroll
        for (int p = 0; p < 2; ++p) {
            const int tp = tid + p * 256;          // group id, g = 4*tp
            float4 f0 = sx4[2 * tp + 0];
            float4 f1 = sx4[2 * tp + 1];
            float4 f2 = sx4[2 * tp + 2];
            float4 f3 = sx4[2 * tp + 3];
            float v[16] = {f0.x,f0.y,f0.z,f0.w, f1.x,f1.y,f1.z,f1.w,
                           f2.x,f2.y,f2.z,f2.w, f3.x,f3.y,f3.z,f3.w};
            float h[8];
            #pragma unroll
            for (int j = 0; j < 8; ++j) {
                float acc = 0.f;
                #pragma unroll
                for (int k = 0; k < 7; ++k)
                    acc = fmaf(v[1 + j + k], wk[k], acc);
                acc = fmaf(acc, inv, bias);                       // BN
                acc = 0.5f * acc * (1.f + erff(acc * INV_SQRT2)); // exact GELU
                h[j] = (acc >= 0.f) ? acc : 0.01f * acc;          // leaky
            }
            float4 Lo;
            float2 Ha, Hb;
            Lo.x = (h[0] + h[1]) * INV_SQRT2;  Ha.x = (h[0] - h[1]) * INV_SQRT2;
            Lo.y = (h[2] + h[3]) * INV_SQRT2;  Ha.y = (h[2] - h[3]) * INV_SQRT2;
            Lo.z = (h[4] + h[5]) * INV_SQRT2;  Hb.x = (h[4] - h[5]) * INV_SQRT2;
            Lo.w = (h[6] + h[7]) * INV_SQRT2;  Hb.y = (h[6] - h[7]) * INV_SQRT2;
            sL4w[tp + 1]     = Lo;   // sL[4tp+4 .. 4tp+7]
            sH2w[2 * tp + 1] = Ha;   // sH[4tp+2 .. 4tp+3]
            sH2w[2 * tp + 2] = Hb;   // sH[4tp+4 .. 4tp+5]
        }
        __syncthreads();

        // ---- phase 2: convs + merge + skip + leaky, 8 outputs/thread-iter ----
        float4* o4 = reinterpret_cast<float4*>(
            out + ((size_t)(b * 128 + oc) << 12));
        #pragma unroll
        for (int p = 0; p < 2; ++p) {
            const int tp = tid + p * 256;          // group id, g = 4*tp
            float4 l0 = sL4[tp + 0];
            float4 l1 = sL4[tp + 1];
            float4 l2 = sL4[tp + 2];
            float a[12] = {l0.x,l0.y,l0.z,l0.w, l1.x,l1.y,l1.z,l1.w,
                           l2.x,l2.y,l2.z,l2.w};
            float4 q0 = sH4[tp + 0];
            float4 q1 = sH4[tp + 1];
            float bb[8] = {q0.x,q0.y,q0.z,q0.w, q1.x,q1.y,q1.z,q1.w};
            float4 s0 = sx4[2 * tp + 1];           // x[2g .. 2g+3]
            float4 s1 = sx4[2 * tp + 2];           // x[2g+4 .. 2g+7]
            float xs[8] = {s0.x,s0.y,s0.z,s0.w, s1.x,s1.y,s1.z,s1.w};

            float o[8];
            #pragma unroll
            for (int m = 0; m < 4; ++m) {
                float yL = 0.f;
                #pragma unroll
                for (int j = 0; j < 7; ++j)
                    yL = fmaf(wL[j], a[1 + m + j], yL);
                float yH = 0.f;
                #pragma unroll
                for (int j = 0; j < 3; ++j)
                    yH = fmaf(wH[j], bb[1 + m + j], yH);
                float re = (yL + yH) * INV_SQRT2;
                float ro = (yL - yH) * INV_SQRT2;
                float e = fmaf(xs[2 * m],     ws, re);
                float d = fmaf(xs[2 * m + 1], ws, ro);
                o[2 * m]     = (e >= 0.f) ? e : 0.01f * e;
                o[2 * m + 1] = (d >= 0.f) ? d : 0.01f * d;
            }
            o4[2 * tp + 0] = make_float4(o[0], o[1], o[2], o[3]);
            o4[2 * tp + 1] = make_float4(o[4], o[5], o[6], o[7]);
        }
        __syncthreads();   // sL/sH reused by next output channel
    }
}

extern "C" void kernel_launch(void* const* d_in, const int* in_sizes, int n_in,
                              void* d_out, int out_size) {
    const float* x     = (const float*)d_in[0];
    const float* w1    = (const float*)d_in[1];
    const float* g1    = (const float*)d_in[2];
    const float* b1    = (const float*)d_in[3];
    const float* m1    = (const float*)d_in[4];
    const float* v1    = (const float*)d_in[5];
    const float* w2L   = (const float*)d_in[6];
    const float* w2H   = (const float*)d_in[7];
    const float* wskip = (const float*)d_in[8];
    float* out = (float*)d_out;

    fused_block_wavelet_down<<<64 * 64, 256>>>(
        x, w1, g1, b1, m1, v1, w2L, w2H, wskip, out);
}

// round 3
// speedup vs baseline: 1.1661x; 1.0858x over previous
#include <cuda_runtime.h>
#include <cuda_bf16.h>

#define INV_SQRT2 0.70710678118654752440f

// Dynamic smem layout (floats):
//   sx  @ 0      len 4104 :  x[t]  at sx[t+4],  zeros [0..3], [4100..4103]
//   sL0 @ 4104   len 2056 :  xL[i] at +4,       zeros [0..3], [2052..2055]
//   sL1 @ 6160   len 2056
//   sH0 @ 8216   len 2052 :  xH[i] at +2,       zeros [0..1], [2050..2051]
//   sH1 @ 10268  len 2052
// total 12320 floats = 49280 bytes
#define SMEM_FLOATS 12320

__device__ __forceinline__ float gelu_leaky(float a) {
    a = 0.5f * a * (1.f + erff(a * INV_SQRT2));   // exact GELU
    return (a >= 0.f) ? a : 0.01f * a;            // LeakyReLU(0.01)
}

// One CTA per (b, cin); produces output channels 2*cin and 2*cin+1,
// sharing every x-window / skip load between the two channels.
__global__ __launch_bounds__(256, 4)
void fused_block_wavelet_down(
    const float* __restrict__ x,      // (64, 64, 4096)
    const float* __restrict__ w1,     // (128, 1, 7)
    const float* __restrict__ g1,
    const float* __restrict__ b1,
    const float* __restrict__ m1,
    const float* __restrict__ v1,
    const float* __restrict__ w2L,    // (128, 1, 7)
    const float* __restrict__ w2H,    // (128, 1, 3)
    const float* __restrict__ wskip,  // (128, 1, 1)
    float* __restrict__ out)          // (64, 128, 4096)
{
    extern __shared__ float smem[];
    float* sx  = smem;
    float* sL0 = smem + 4104;
    float* sL1 = smem + 6160;
    float* sH0 = smem + 8216;
    float* sH1 = smem + 10268;

    const int tid = threadIdx.x;
    const int b   = blockIdx.x >> 6;
    const int cin = blockIdx.x & 63;
    const int oc0 = 2 * cin;

    // zero pad cells (vector stores; indices never overlap real data)
    if (tid == 0) *reinterpret_cast<float4*>(sx)          = make_float4(0,0,0,0);
    if (tid == 1) *reinterpret_cast<float4*>(sx + 4100)   = make_float4(0,0,0,0);
    if (tid == 2) *reinterpret_cast<float4*>(sL0)         = make_float4(0,0,0,0);
    if (tid == 3) *reinterpret_cast<float4*>(sL0 + 2052)  = make_float4(0,0,0,0);
    if (tid == 4) *reinterpret_cast<float4*>(sL1)         = make_float4(0,0,0,0);
    if (tid == 5) *reinterpret_cast<float4*>(sL1 + 2052)  = make_float4(0,0,0,0);
    if (tid == 6) *reinterpret_cast<float2*>(sH0)         = make_float2(0,0);
    if (tid == 7) *reinterpret_cast<float2*>(sH0 + 2050)  = make_float2(0,0);
    if (tid == 8) *reinterpret_cast<float2*>(sH1)         = make_float2(0,0);
    if (tid == 9) *reinterpret_cast<float2*>(sH1 + 2050)  = make_float2(0,0);

    // load x row: LDG.128 -> STS.128, lane-contiguous
    {
        const float4* x4 = reinterpret_cast<const float4*>(
            x + ((size_t)(b * 64 + cin) << 12));
        float4* sxw = reinterpret_cast<float4*>(sx + 4);
        #pragma unroll
        for (int p = 0; p < 4; ++p)
            sxw[tid + p * 256] = x4[tid + p * 256];
    }

    // phase-1 weights (both channels)
    float wk0[7], wk1[7];
    #pragma unroll
    for (int k = 0; k < 7; ++k) { wk0[k] = w1[oc0 * 7 + k]; wk1[k] = w1[oc0 * 7 + 7 + k]; }
    const float inv0  = g1[oc0] * rsqrtf(v1[oc0] + 1e-5f);
    const float bias0 = b1[oc0] - m1[oc0] * inv0;
    const float inv1  = g1[oc0 + 1] * rsqrtf(v1[oc0 + 1] + 1e-5f);
    const float bias1 = b1[oc0 + 1] - m1[oc0 + 1] * inv1;

    __syncthreads();

    const float4* sx4 = reinterpret_cast<const float4*>(sx);

    // ---- phase 1: conv7 + BN + GELU + leaky + Haar split, both channels ----
    #pragma unroll 1
    for (int p = 0; p < 4; ++p) {
        const int tp = tid + p * 256;           // 0..1023; h positions 4tp..4tp+3
        float4 f0 = sx4[tp];                    // conflict-free, lane-contiguous
        float4 f1 = sx4[tp + 1];
        float4 f2 = sx4[tp + 2];
        float v[12] = {f0.x,f0.y,f0.z,f0.w, f1.x,f1.y,f1.z,f1.w,
                       f2.x,f2.y,f2.z,f2.w};   // v[i] = x[4tp-4+i]

        float h[4];
        #pragma unroll
        for (int j = 0; j < 4; ++j) {
            float a = 0.f;
            #pragma unroll
            for (int k = 0; k < 7; ++k) a = fmaf(v[1 + j + k], wk0[k], a);
            h[j] = gelu_leaky(fmaf(a, inv0, bias0));
        }
        reinterpret_cast<float2*>(sL0)[tp + 2] =
            make_float2((h[0] + h[1]) * INV_SQRT2, (h[2] + h[3]) * INV_SQRT2);
        reinterpret_cast<float2*>(sH0)[tp + 1] =
            make_float2((h[0] - h[1]) * INV_SQRT2, (h[2] - h[3]) * INV_SQRT2);

        #pragma unroll
        for (int j = 0; j < 4; ++j) {
            float a = 0.f;
            #pragma unroll
            for (int k = 0; k < 7; ++k) a = fmaf(v[1 + j + k], wk1[k], a);
            h[j] = gelu_leaky(fmaf(a, inv1, bias1));
        }
        reinterpret_cast<float2*>(sL1)[tp + 2] =
            make_float2((h[0] + h[1]) * INV_SQRT2, (h[2] + h[3]) * INV_SQRT2);
        reinterpret_cast<float2*>(sH1)[tp + 1] =
            make_float2((h[0] - h[1]) * INV_SQRT2, (h[2] - h[3]) * INV_SQRT2);
    }

    // phase-2 weights (wk/BN regs are dead now)
    float wL0[7], wL1[7], wH0[3], wH1[3];
    #pragma unroll
    for (int k = 0; k < 7; ++k) { wL0[k] = w2L[oc0 * 7 + k]; wL1[k] = w2L[oc0 * 7 + 7 + k]; }
    #pragma unroll
    for (int k = 0; k < 3; ++k) { wH0[k] = w2H[oc0 * 3 + k]; wH1[k] = w2H[oc0 * 3 + 3 + k]; }
    const float ws0 = wskip[oc0];
    const float ws1 = wskip[oc0 + 1];

    __syncthreads();

    // ---- phase 2: conv7L/conv3H + merge + skip + leaky, both channels ----
    float4* o0 = reinterpret_cast<float4*>(out + ((size_t)(b * 128 + oc0) << 12));
    float4* o1 = reinterpret_cast<float4*>(out + ((size_t)(b * 128 + oc0 + 1) << 12));

    #pragma unroll 1
    for (int p = 0; p < 4; ++p) {
        const int tp = tid + p * 256;           // output float4 index
        const float4 sk = sx4[tp + 1];          // x[4tp..4tp+3], conflict-free

        #pragma unroll
        for (int u = 0; u < 2; ++u) {
            const float* sL = u ? sL1 : sL0;
            const float* sH = u ? sH1 : sH0;
            const float* wL = u ? wL1 : wL0;
            const float* wH = u ? wH1 : wH0;
            const float  ws = u ? ws1 : ws0;

            // sL floats [2tp .. 2tp+9] via 5 lane-contiguous LDS.64
            float la[10];
            #pragma unroll
            for (int c = 0; c < 5; ++c) {
                float2 t = reinterpret_cast<const float2*>(sL)[tp + c];
                la[2 * c] = t.x; la[2 * c + 1] = t.y;
            }
            // sH floats [2tp .. 2tp+5] via 3 lane-contiguous LDS.64
            float ha[6];
            #pragma unroll
            for (int c = 0; c < 3; ++c) {
                float2 t = reinterpret_cast<const float2*>(sH)[tp + c];
                ha[2 * c] = t.x; ha[2 * c + 1] = t.y;
            }

            // pair i0 = 2tp: window sL[2tp+1..2tp+7] -> la[1..7]; sH[2tp+1..2tp+3] -> ha[1..3]
            float yL0 = 0.f, yL1 = 0.f;
            #pragma unroll
            for (int j = 0; j < 7; ++j) {
                yL0 = fmaf(wL[j], la[1 + j], yL0);
                yL1 = fmaf(wL[j], la[2 + j], yL1);
            }
            float yH0 = 0.f, yH1 = 0.f;
            #pragma unroll
            for (int j = 0; j < 3; ++j) {
                yH0 = fmaf(wH[j], ha[1 + j], yH0);
                yH1 = fmaf(wH[j], ha[2 + j], yH1);
            }

            float4 o;
            o.x = fmaf(sk.x, ws, (yL0 + yH0) * INV_SQRT2);
            o.y = fmaf(sk.y, ws, (yL0 - yH0) * INV_SQRT2);
            o.z = fmaf(sk.z, ws, (yL1 + yH1) * INV_SQRT2);
            o.w = fmaf(sk.w, ws, (yL1 - yH1) * INV_SQRT2);
            o.x = (o.x >= 0.f) ? o.x : 0.01f * o.x;
            o.y = (o.y >= 0.f) ? o.y : 0.01f * o.y;
            o.z = (o.z >= 0.f) ? o.z : 0.01f * o.z;
            o.w = (o.w >= 0.f) ? o.w : 0.01f * o.w;
            (u ? o1 : o0)[tp] = o;
        }
    }
}

extern "C" void kernel_launch(void* const* d_in, const int* in_sizes, int n_in,
                              void* d_out, int out_size) {
    const float* x     = (const float*)d_in[0];
    const float* w1    = (const float*)d_in[1];
    const float* g1    = (const float*)d_in[2];
    const float* b1    = (const float*)d_in[3];
    const float* m1    = (const float*)d_in[4];
    const float* v1    = (const float*)d_in[5];
    const float* w2L   = (const float*)d_in[6];
    const float* w2H   = (const float*)d_in[7];
    const float* wskip = (const float*)d_in[8];
    float* out = (float*)d_out;

    const int smem_bytes = SMEM_FLOATS * (int)sizeof(float);
    static bool attr_set = false;
    if (!attr_set) {
        cudaFuncSetAttribute(fused_block_wavelet_down,
                             cudaFuncAttributeMaxDynamicSharedMemorySize,
                             smem_bytes);
        attr_set = true;
    }
    fused_block_wavelet_down<<<64 * 64, 256, smem_bytes>>>(
        x, w1, g1, b1, m1, v1, w2L, w2H, wskip, out);
}